// round 7
// baseline (speedup 1.0000x reference)
#include <cuda_runtime.h>
#include <cuda_bf16.h>
#include <cstdint>

// Problem constants
#define Bz   4
#define Az   3
#define Sz   1024
#define Hz   768
#define NHz  12
#define HDz  64

typedef unsigned long long u64;

// -------------------- scratch (device globals; no allocation) --------------------
__device__ __nv_bfloat16 g_Qh [Bz*NHz*Sz*HDz],    g_Ql [Bz*NHz*Sz*HDz];    // [b][h][s][d] (x 1/8)
__device__ __nv_bfloat16 g_Kh [Bz*NHz*Az*Sz*HDz], g_Kl [Bz*NHz*Az*Sz*HDz]; // [b][h][a][s][d]
__device__ __nv_bfloat16 g_Vth[Bz*NHz*Az*HDz*Sz], g_Vtl[Bz*NHz*Az*HDz*Sz]; // [b][h][a][d][s]
__device__ float g_att[Bz*Sz*Hz];                                          // attended fp32
__device__ float g_res[Bz*Sz*Hz];                                          // pre-LN fp32

// SW64 swizzle for 64-byte SMEM rows
#define SWZ64(o) ((o) ^ (((o) >> 3) & 0x30))

__device__ __forceinline__ uint32_t smem_u32(const void* p) {
    uint32_t a;
    asm("{ .reg .u64 t; cvta.to.shared.u64 t, %1; cvt.u32.u64 %0, t; }"
        : "=r"(a) : "l"(p));
    return a;
}
__device__ __forceinline__ void ldsm_x4(uint32_t* f, uint32_t a) {
    asm volatile("ldmatrix.sync.aligned.m8n8.x4.shared.b16 {%0,%1,%2,%3}, [%4];"
                 : "=r"(f[0]), "=r"(f[1]), "=r"(f[2]), "=r"(f[3]) : "r"(a));
}
__device__ __forceinline__ void mma16816(float* d, const uint32_t* a, const uint32_t* b) {
    asm volatile("mma.sync.aligned.m16n8k16.row.col.f32.bf16.bf16.f32 "
                 "{%0,%1,%2,%3}, {%4,%5,%6,%7}, {%8,%9}, {%0,%1,%2,%3};"
                 : "+f"(d[0]), "+f"(d[1]), "+f"(d[2]), "+f"(d[3])
                 : "r"(a[0]), "r"(a[1]), "r"(a[2]), "r"(a[3]), "r"(b[0]), "r"(b[1]));
}
__device__ __forceinline__ void cpa16(uint32_t dst, const void* src) {
    asm volatile("cp.async.cg.shared.global [%0], [%1], 16;" :: "r"(dst), "l"(src));
}
#define CP_COMMIT() asm volatile("cp.async.commit_group;" ::: "memory")
#define CP_WAIT(n)  asm volatile("cp.async.wait_group %0;" :: "n"(n) : "memory")

// fp32 float4 -> (bf16 hi x4, bf16 lo x4) packed as 2x uint2
__device__ __forceinline__ void cvt_split(float4 v, uint2& hi, uint2& lo) {
    uint32_t h0, h1;
    asm("cvt.rn.bf16x2.f32 %0, %1, %2;" : "=r"(h0) : "f"(v.y), "f"(v.x));
    asm("cvt.rn.bf16x2.f32 %0, %1, %2;" : "=r"(h1) : "f"(v.w), "f"(v.z));
    float hx = __uint_as_float(h0 << 16);
    float hy = __uint_as_float(h0 & 0xffff0000u);
    float hz = __uint_as_float(h1 << 16);
    float hw = __uint_as_float(h1 & 0xffff0000u);
    uint32_t l0, l1;
    asm("cvt.rn.bf16x2.f32 %0, %1, %2;" : "=r"(l0) : "f"(v.y - hy), "f"(v.x - hx));
    asm("cvt.rn.bf16x2.f32 %0, %1, %2;" : "=r"(l1) : "f"(v.w - hw), "f"(v.z - hz));
    hi = make_uint2(h0, h1);
    lo = make_uint2(l0, l1);
}
// fp32 pair -> bf16x2 hi + bf16x2 lo
__device__ __forceinline__ void split2(float x, float y, uint32_t& hi, uint32_t& lo) {
    asm("cvt.rn.bf16x2.f32 %0, %1, %2;" : "=r"(hi) : "f"(y), "f"(x));
    float hx = __uint_as_float(hi << 16);
    float hy = __uint_as_float(hi & 0xffff0000u);
    asm("cvt.rn.bf16x2.f32 %0, %1, %2;" : "=r"(lo) : "f"(y - hy), "f"(x - hx));
}

// ==================== projection GEMM: fp32 in, convert-in-loader, 3-buf/1-barrier ====================
// out[m][n] = sum_k X[m][k] * W[n][k]
// MODE 0: X=query -> g_Qh/l (x0.125)  MODE 1: X=adap -> g_Kh/l
// MODE 2: X=adap -> g_Vth/l (transposed)  MODE 3: X=g_att -> g_res (+bias+resid)
#define GMM_SMEM (3 * 32768)

__device__ __forceinline__ void gmm_store(char* sm, uint32_t bufoff, int lr, int lc,
                                          const float4* aR, const float4* bR)
{
#pragma unroll
    for (int i = 0; i < 4; i++) {
        uint2 hi, lo; cvt_split(aR[i], hi, lo);
        uint32_t off = SWZ64((uint32_t)(lr + 32 * i) * 64u + (uint32_t)lc * 8u);
        *(uint2*)(sm + bufoff + off)        = hi;
        *(uint2*)(sm + bufoff + 8192 + off) = lo;
    }
#pragma unroll
    for (int i = 0; i < 4; i++) {
        uint2 hi, lo; cvt_split(bR[i], hi, lo);
        uint32_t off = SWZ64((uint32_t)(lr + 32 * i) * 64u + (uint32_t)lc * 8u);
        *(uint2*)(sm + bufoff + 16384 + off) = hi;
        *(uint2*)(sm + bufoff + 24576 + off) = lo;
    }
}

template <int MODE>
__global__ void __launch_bounds__(256)
gemm_f32(const float* __restrict__ X, const float* __restrict__ W,
         const float* __restrict__ bias, const float* __restrict__ resid)
{
    extern __shared__ char sm[];
    const uint32_t sb = smem_u32(sm);
    const int tid = threadIdx.x, lane = tid & 31, w = tid >> 5;
    const int wm = w >> 2, wn = w & 3;
    const int m0 = blockIdx.x * 128, n0 = blockIdx.y * 128;

    const float* Xs = (MODE == 3) ? (const float*)g_att : X;
    const int lr = tid >> 3, lc = tid & 7;
    const float* Ag = Xs + (size_t)(m0 + lr) * Hz + lc * 4;
    const float* Bg = W  + (size_t)(n0 + lr) * Hz + lc * 4;

    float4 aR[4], bR[4];
#pragma unroll
    for (int i = 0; i < 4; i++) { aR[i] = *(const float4*)(Ag + (size_t)i * 32 * Hz);
                                  bR[i] = *(const float4*)(Bg + (size_t)i * 32 * Hz); }
    gmm_store(sm, 0, lr, lc, aR, bR);
#pragma unroll
    for (int i = 0; i < 4; i++) { aR[i] = *(const float4*)(Ag + (size_t)i * 32 * Hz + 32);
                                  bR[i] = *(const float4*)(Bg + (size_t)i * 32 * Hz + 32); }

    float acc[4][4][4];
#pragma unroll
    for (int a = 0; a < 4; a++)
#pragma unroll
        for (int b = 0; b < 4; b++)
#pragma unroll
            for (int c = 0; c < 4; c++) acc[a][b][c] = 0.0f;

    const int arow = lane & 15;
    const int akb  = (lane >> 4) << 4;
    const int brow = (lane & 7) + ((lane & 16) >> 1);
    const int bkb  = (lane & 8) << 1;

    for (int s = 0; s < 24; s++) {
        // regs hold stage s+1; store it, prefetch stage s+2, one barrier, compute s.
        if (s + 1 < 24) gmm_store(sm, (uint32_t)((s + 1) % 3) * 32768u, lr, lc, aR, bR);
        if (s + 2 < 24) {
            const int ko = (s + 2) * 32;
#pragma unroll
            for (int i = 0; i < 4; i++) { aR[i] = *(const float4*)(Ag + (size_t)i * 32 * Hz + ko);
                                          bR[i] = *(const float4*)(Bg + (size_t)i * 32 * Hz + ko); }
        }
        __syncthreads();

        const uint32_t base = sb + (uint32_t)(s % 3) * 32768u;
#pragma unroll
        for (int k16 = 0; k16 < 2; k16++) {
            const int kof = k16 * 32;
            uint32_t fa[4][4], fbh[2][4], fbl[2][4];
#pragma unroll
            for (int mi = 0; mi < 4; mi++) {
                uint32_t off = (uint32_t)((wm * 64 + mi * 16 + arow) * 64 + kof + akb);
                ldsm_x4(fa[mi], base + SWZ64(off));
            }
#pragma unroll
            for (int ni = 0; ni < 2; ni++) {
                uint32_t off = (uint32_t)((wn * 32 + ni * 16 + brow) * 64 + kof + bkb);
                ldsm_x4(fbh[ni], base + 16384u + SWZ64(off));
                ldsm_x4(fbl[ni], base + 24576u + SWZ64(off));
            }
#pragma unroll
            for (int mi = 0; mi < 4; mi++)
#pragma unroll
                for (int ni = 0; ni < 4; ni++) {
                    mma16816(acc[mi][ni], fa[mi], &fbh[ni >> 1][(ni & 1) * 2]);
                    mma16816(acc[mi][ni], fa[mi], &fbl[ni >> 1][(ni & 1) * 2]);
                }
#pragma unroll
            for (int mi = 0; mi < 4; mi++) {
                uint32_t off = (uint32_t)((wm * 64 + mi * 16 + arow) * 64 + kof + akb);
                ldsm_x4(fa[mi], base + 8192u + SWZ64(off));
            }
#pragma unroll
            for (int mi = 0; mi < 4; mi++)
#pragma unroll
                for (int ni = 0; ni < 4; ni++)
                    mma16816(acc[mi][ni], fa[mi], &fbh[ni >> 1][(ni & 1) * 2]);
        }
    }

    // ---- epilogue ----
    const int g = lane >> 2, t = lane & 3;
#pragma unroll
    for (int ni = 0; ni < 4; ni++) {
        const int col = n0 + wn * 32 + ni * 8 + 2 * t;
        const float2 bs = *(const float2*)(bias + col);
#pragma unroll
        for (int mi = 0; mi < 4; mi++) {
            const int r0 = m0 + wm * 64 + mi * 16 + g;
#pragma unroll
            for (int half = 0; half < 2; half++) {
                const int row = r0 + half * 8;
                float vx = acc[mi][ni][half * 2 + 0] + bs.x;
                float vy = acc[mi][ni][half * 2 + 1] + bs.y;
                if (MODE == 0) {
                    const int b = row >> 10, ss = row & 1023;
                    const int h = col >> 6, d = col & 63;
                    uint32_t hi, lo; split2(vx * 0.125f, vy * 0.125f, hi, lo);
                    size_t off = (((size_t)(b * NHz + h)) * Sz + ss) * HDz + d;
                    *(uint32_t*)(g_Qh + off) = hi;
                    *(uint32_t*)(g_Ql + off) = lo;
                } else if (MODE == 1) {
                    const int b = row / (Az * Sz), rr = row - b * (Az * Sz);
                    const int a = rr >> 10, ss = rr & 1023;
                    const int h = col >> 6, d = col & 63;
                    uint32_t hi, lo; split2(vx, vy, hi, lo);
                    size_t off = ((((size_t)(b * NHz + h)) * Az + a) * Sz + ss) * HDz + d;
                    *(uint32_t*)(g_Kh + off) = hi;
                    *(uint32_t*)(g_Kl + off) = lo;
                } else if (MODE == 2) {
                    const int b = row / (Az * Sz), rr = row - b * (Az * Sz);
                    const int a = rr >> 10, ss = rr & 1023;
                    const int h = col >> 6, d = col & 63;
                    uint32_t hi, lo; split2(vx, vy, hi, lo);
                    size_t off = ((((size_t)(b * NHz + h)) * Az + a) * HDz + d) * Sz + ss;
                    uint16_t* ph = (uint16_t*)(g_Vth + off);
                    uint16_t* pl = (uint16_t*)(g_Vtl + off);
                    ph[0]  = (uint16_t)hi;  ph[Sz] = (uint16_t)(hi >> 16);
                    pl[0]  = (uint16_t)lo;  pl[Sz] = (uint16_t)(lo >> 16);
                } else {
                    const float2 q = *(const float2*)(resid + (size_t)row * Hz + col);
                    *(float2*)(g_res + (size_t)row * Hz + col)
                        = make_float2(vx + q.x, vy + q.y);
                }
            }
        }
    }
}

// -------------------- fast exp2 / rcp --------------------
__device__ __forceinline__ float fexp2(float x) {
    x = fmaxf(x, -120.0f);
    float n = floorf(x);
    float f = x - n;
    float p =             1.5404e-4f;
    p = fmaf(p, f, 1.3333558e-3f);
    p = fmaf(p, f, 9.6181291e-3f);
    p = fmaf(p, f, 5.5504109e-2f);
    p = fmaf(p, f, 2.4022651e-1f);
    p = fmaf(p, f, 6.9314718e-1f);
    p = fmaf(p, f, 1.0f);
    int e = (int)n;
    float sc = __int_as_float((e + 127) << 23);
    return p * sc;
}
__device__ __forceinline__ float frcp(float s) {
    float x = __int_as_float(0x7EF311C3u - __float_as_int(s));
    x = x * fmaf(-s, x, 2.0f);
    x = x * fmaf(-s, x, 2.0f);
    x = x * fmaf(-s, x, 2.0f);
    return x;
}
__device__ __forceinline__ void softmax3(float& a, float& b, float& c) {
    const float L2E = 1.4426950408889634f;
    float m  = fmaxf(a, fmaxf(b, c));
    float mL = m * L2E;
    float e0 = fexp2(fmaf(a, L2E, -mL));
    float e1 = fexp2(fmaf(b, L2E, -mL));
    float e2 = fexp2(fmaf(c, L2E, -mL));
    float r  = frcp(e0 + e1 + e2);
    a = e0 * r; b = e1 * r; c = e2 * r;
}

// ==================== attention: P-in-registers, Q-frags hoisted, 1 barrier/iter ====================
#define ATT_SMEM 229376

__global__ void __launch_bounds__(256, 1)
attn_mma()
{
    extern __shared__ char sm[];
    const uint32_t sb = smem_u32(sm);
    const int tid = threadIdx.x, lane = tid & 31, w = tid >> 5;
    const int b = blockIdx.z, h = blockIdx.y, q0 = blockIdx.x * 128;
    const size_t bh = (size_t)(b * NHz + h);

    const __nv_bfloat16* Qh = g_Qh  + bh * Sz * HDz;
    const __nv_bfloat16* Ql = g_Ql  + bh * Sz * HDz;
    const __nv_bfloat16* Kh = g_Kh  + bh * Az * Sz * HDz;
    const __nv_bfloat16* Kl = g_Kl  + bh * Az * Sz * HDz;
    const __nv_bfloat16* Vh = g_Vth + bh * Az * HDz * Sz;
    const __nv_bfloat16* Vl = g_Vtl + bh * Az * HDz * Sz;

    auto issue_kv = [&](int s0, uint32_t SB) {
#pragma unroll
        for (int i = 0; i < 12; i++) {
            int j = tid + i * 256;
            int comp = j >> 9;
            int a = comp >> 1, hl = comp & 1;
            int cj = j & 511;
            int row = cj >> 3, c = cj & 7;
            uint32_t dst = SB + (uint32_t)a * 16384u + (uint32_t)hl * 8192u
                         + (uint32_t)(c >> 2) * 4096u
                         + SWZ64((uint32_t)row * 64u + (uint32_t)(c & 3) * 16u);
            const __nv_bfloat16* ks = (hl ? Kl : Kh) + (size_t)a * Sz * HDz
                                     + (size_t)(s0 + row) * HDz + c * 8;
            cpa16(dst, ks);
            const __nv_bfloat16* vs = (hl ? Vl : Vh) + (size_t)a * HDz * Sz
                                     + (size_t)row * Sz + s0 + c * 8;
            cpa16(dst + 49152u, vs);
        }
    };

    // prologue: Q + K/V stage 0
#pragma unroll
    for (int i = 0; i < 4; i++) {
        int j = tid + i * 256;
        int row = j >> 3, c = j & 7;
        uint32_t dst = (uint32_t)(c >> 2) * 8192u
                     + SWZ64((uint32_t)row * 64u + (uint32_t)(c & 3) * 16u);
        cpa16(sb + dst,          Qh + (size_t)(q0 + row) * HDz + c * 8);
        cpa16(sb + 16384u + dst, Ql + (size_t)(q0 + row) * HDz + c * 8);
    }
    issue_kv(0, sb + 32768u);
    CP_COMMIT();

    const int arow = lane & 15;
    const int akb  = (lane >> 4) << 4;
    const int brow = (lane & 7) + ((lane & 16) >> 1);
    const int bkb  = (lane & 8) << 1;
    const int g = lane >> 2, t = lane & 3;

    CP_WAIT(0);
    __syncthreads();

    // hoist Q fragments (constant over the s-loop)
    uint32_t qfh[4][4], qfl[4][4];
#pragma unroll
    for (int kk = 0; kk < 4; kk++) {
        uint32_t aoff = (uint32_t)(kk >> 1) * 8192u
                      + SWZ64((uint32_t)(w * 16 + arow) * 64u + (uint32_t)(kk & 1) * 32u + akb);
        ldsm_x4(qfh[kk], sb + aoff);
        ldsm_x4(qfl[kk], sb + 16384u + aoff);
    }
    issue_kv(64, sb + 131072u);
    CP_COMMIT();

    float o[8][4];
#pragma unroll
    for (int n8 = 0; n8 < 8; n8++)
#pragma unroll
        for (int e = 0; e < 4; e++) o[n8][e] = 0.0f;

    for (int ti = 0; ti < 16; ti++) {
        if (ti > 0) {
            CP_WAIT(0);
            __syncthreads();   // all warps done with buffer (ti+1)&1 (read at ti-1)
            if (ti + 1 < 16) { issue_kv((ti + 1) * 64, sb + 32768u + (uint32_t)((ti + 1) & 1) * 98304u); CP_COMMIT(); }
        }

        const uint32_t KB = sb + 32768u + (uint32_t)(ti & 1) * 98304u;
        const uint32_t VB = KB + 49152u;

        // ---- scores ----
        float acc[3][8][4];
#pragma unroll
        for (int a = 0; a < 3; a++)
#pragma unroll
            for (int n8 = 0; n8 < 8; n8++)
#pragma unroll
                for (int e = 0; e < 4; e++) acc[a][n8][e] = 0.0f;

#pragma unroll
        for (int kk = 0; kk < 4; kk++) {
#pragma unroll
            for (int a = 0; a < 3; a++) {
                uint32_t kbase = KB + (uint32_t)a * 16384u + (uint32_t)(kk >> 1) * 4096u;
#pragma unroll
                for (int sg = 0; sg < 4; sg++) {
                    uint32_t boff = SWZ64((uint32_t)(sg * 16 + brow) * 64u
                                          + (uint32_t)(kk & 1) * 32u + bkb);
                    uint32_t fbh[4], fbl[4];
                    ldsm_x4(fbh, kbase + boff);
                    ldsm_x4(fbl, kbase + 8192u + boff);
#pragma unroll
                    for (int nn = 0; nn < 2; nn++) {
                        mma16816(acc[a][sg * 2 + nn], qfh[kk], &fbh[nn * 2]);
                        mma16816(acc[a][sg * 2 + nn], qfh[kk], &fbl[nn * 2]);
                        mma16816(acc[a][sg * 2 + nn], qfl[kk], &fbh[nn * 2]);
                    }
                }
            }
        }

        // ---- softmax over adapter axis ----
#pragma unroll
        for (int n8 = 0; n8 < 8; n8++)
#pragma unroll
            for (int e = 0; e < 4; e++)
                softmax3(acc[0][n8][e], acc[1][n8][e], acc[2][n8][e]);

        // ---- PV ----
#pragma unroll
        for (int a = 0; a < 3; a++) {
            uint32_t ph[4][4], pl[4][4];
#pragma unroll
            for (int kc = 0; kc < 4; kc++) {
                split2(acc[a][kc*2][0],   acc[a][kc*2][1],   ph[kc][0], pl[kc][0]);
                split2(acc[a][kc*2][2],   acc[a][kc*2][3],   ph[kc][1], pl[kc][1]);
                split2(acc[a][kc*2+1][0], acc[a][kc*2+1][1], ph[kc][2], pl[kc][2]);
                split2(acc[a][kc*2+1][2], acc[a][kc*2+1][3], ph[kc][3], pl[kc][3]);
            }
            uint32_t vbA = VB + (uint32_t)a * 16384u;
#pragma unroll
            for (int kc = 0; kc < 4; kc++) {
                uint32_t vbase = vbA + (uint32_t)(kc >> 1) * 4096u;
#pragma unroll
                for (int dg = 0; dg < 4; dg++) {
                    uint32_t boff = SWZ64((uint32_t)(dg * 16 + brow) * 64u
                                          + (uint32_t)(kc & 1) * 32u + bkb);
                    uint32_t fbh[4], fbl[4];
                    ldsm_x4(fbh, vbase + boff);
                    ldsm_x4(fbl, vbase + 8192u + boff);
#pragma unroll
                    for (int nn = 0; nn < 2; nn++) {
                        mma16816(o[dg * 2 + nn], ph[kc], &fbh[nn * 2]);
                        mma16816(o[dg * 2 + nn], ph[kc], &fbl[nn * 2]);
                        mma16816(o[dg * 2 + nn], pl[kc], &fbh[nn * 2]);
                    }
                }
            }
        }
    }

    // ---- epilogue: attended -> g_att (fp32) ----
    const int q = q0 + w * 16 + g;
#pragma unroll
    for (int n8 = 0; n8 < 8; n8++) {
        const int col = h * 64 + n8 * 8 + 2 * t;
        *(float2*)(g_att + ((size_t)b * Sz + q) * Hz + col)     = make_float2(o[n8][0], o[n8][1]);
        *(float2*)(g_att + ((size_t)b * Sz + q + 8) * Hz + col) = make_float2(o[n8][2], o[n8][3]);
    }
}

// -------------------- LayerNorm over H=768 per row --------------------
__global__ void __launch_bounds__(256)
ln_kernel(const float* __restrict__ gamma, const float* __restrict__ beta,
          float* __restrict__ out)
{
    const int row = blockIdx.x;
    const int tid = threadIdx.x;
    const float* x = g_res + (size_t)row * Hz;

    float v0 = x[tid], v1 = x[tid + 256], v2 = x[tid + 512];
    float s  = v0 + v1 + v2;
    float ss = v0 * v0 + v1 * v1 + v2 * v2;

    __shared__ float rs[8], rss[8];
#pragma unroll
    for (int o = 16; o; o >>= 1) {
        s  += __shfl_xor_sync(0xffffffffu, s,  o);
        ss += __shfl_xor_sync(0xffffffffu, ss, o);
    }
    if ((tid & 31) == 0) { rs[tid >> 5] = s; rss[tid >> 5] = ss; }
    __syncthreads();
    if (tid == 0) {
        float S = 0.f, SS = 0.f;
#pragma unroll
        for (int i = 0; i < 8; i++) { S += rs[i]; SS += rss[i]; }
        rs[0] = S; rss[0] = SS;
    }
    __syncthreads();
    float mu  = rs[0]  * (1.0f / 768.0f);
    float var = rss[0] * (1.0f / 768.0f) - mu * mu;
    float inv = rsqrtf(var + 1e-5f);

    float* o = out + (size_t)row * Hz;
    o[tid]       = (v0 - mu) * inv * gamma[tid]       + beta[tid];
    o[tid + 256] = (v1 - mu) * inv * gamma[tid + 256] + beta[tid + 256];
    o[tid + 512] = (v2 - mu) * inv * gamma[tid + 512] + beta[tid + 512];
}

// -------------------- avg_weights == 1/3 analytically --------------------
__global__ void __launch_bounds__(256)
fill_third(float* __restrict__ p)
{
    size_t i = (size_t)blockIdx.x * 256 + threadIdx.x;
    const float t = 1.0f / 3.0f;
    ((float4*)p)[i] = make_float4(t, t, t, t);
}

// -------------------- launch --------------------
extern "C" void kernel_launch(void* const* d_in, const int* in_sizes, int n_in,
                              void* d_out, int out_size)
{
    const float* query = (const float*)d_in[0];
    const float* adap  = (const float*)d_in[1];
    const float* Wq    = (const float*)d_in[2];
    const float* bq    = (const float*)d_in[3];
    const float* Wk    = (const float*)d_in[4];
    const float* bk    = (const float*)d_in[5];
    const float* Wv    = (const float*)d_in[6];
    const float* bv    = (const float*)d_in[7];
    const float* Wo    = (const float*)d_in[8];
    const float* bo    = (const float*)d_in[9];
    const float* gamma = (const float*)d_in[10];
    const float* beta  = (const float*)d_in[11];

    float* out = (float*)d_out;
    float* avg = out + (size_t)Bz * Sz * Hz;

    cudaFuncSetAttribute(attn_mma,    cudaFuncAttributeMaxDynamicSharedMemorySize, ATT_SMEM);
    cudaFuncSetAttribute(gemm_f32<0>, cudaFuncAttributeMaxDynamicSharedMemorySize, GMM_SMEM);
    cudaFuncSetAttribute(gemm_f32<1>, cudaFuncAttributeMaxDynamicSharedMemorySize, GMM_SMEM);
    cudaFuncSetAttribute(gemm_f32<2>, cudaFuncAttributeMaxDynamicSharedMemorySize, GMM_SMEM);
    cudaFuncSetAttribute(gemm_f32<3>, cudaFuncAttributeMaxDynamicSharedMemorySize, GMM_SMEM);

    dim3 blk(256);

    // avg_weights = 1/3
    fill_third<<<(Bz * Sz * Sz) / 4 / 256, blk>>>(avg);

    // projections (fp32 in, convert in loader)
    gemm_f32<0><<<dim3((Bz * Sz) / 128, Hz / 128),      blk, GMM_SMEM>>>(query, Wq, bq, nullptr);
    gemm_f32<1><<<dim3((Bz * Az * Sz) / 128, Hz / 128), blk, GMM_SMEM>>>(adap,  Wk, bk, nullptr);
    gemm_f32<2><<<dim3((Bz * Az * Sz) / 128, Hz / 128), blk, GMM_SMEM>>>(adap,  Wv, bv, nullptr);

    // attention
    attn_mma<<<dim3(Sz / 128, NHz, Bz), blk, ATT_SMEM>>>();

    // output projection + residual, then LayerNorm
    gemm_f32<3><<<dim3((Bz * Sz) / 128, Hz / 128), blk, GMM_SMEM>>>(nullptr, Wo, bo, query);
    ln_kernel<<<Bz * Sz, blk>>>(gamma, beta, out);
}